// round 3
// baseline (speedup 1.0000x reference)
#include <cuda_runtime.h>
#include <math.h>

#define BATCH 2
#define SEQ   2048
#define EMB   1024
#define NH    16
#define HD    64
#define MROWS (BATCH*SEQ)   // 4096
#define FS    68            // padded smem row stride (floats) for flash tiles

// Scratch (allocation-free): Q,K,V in [B,H,T,D] packed as [(b*NH+h)*SEQ+t][HD];
// O (attention output) in [B,T,C] row-major.
__device__ float g_Q[MROWS*EMB];
__device__ float g_K[MROWS*EMB];
__device__ float g_V[MROWS*EMB];
__device__ float g_O[MROWS*EMB];

// Core 128x128x16 register-tiled GEMM body: C[M,N] = A[M,K] @ W[K,N] + bias.
// PERMUTE=1 scatters output into [B,H,T,D].
template<int PERMUTE>
__device__ __forceinline__ void gemm_body(
    const float* __restrict__ A, const float* __restrict__ W,
    const float* __restrict__ bias, float* __restrict__ C,
    int M, int N, int K, int m0, int n0)
{
    __shared__ float As[16][128];   // [k][m] (transposed on store)
    __shared__ float Bs[16][128];   // [k][n]

    const int tid = threadIdx.x;
    const int tx  = tid & 15;
    const int ty  = tid >> 4;

    // load assignments
    const int ar  = tid >> 2;          // 0..63 (row), second half +64
    const int akv = (tid & 3) << 2;    // k base 0,4,8,12
    const int bkr = tid >> 5;          // 0..7 (k row), second +8
    const int bnv = (tid & 31) << 2;   // n base 0..124

    const float* Ap0 = A + (size_t)(m0 + ar) * K + akv;
    const float* Ap1 = Ap0 + (size_t)64 * K;
    const float* Bp0 = W + (size_t)bkr * N + n0 + bnv;
    const float* Bp1 = Bp0 + (size_t)8 * N;

    float4 a0 = *(const float4*)Ap0;
    float4 a1 = *(const float4*)Ap1;
    float4 b0 = *(const float4*)Bp0;
    float4 b1 = *(const float4*)Bp1;

    float acc[2][2][4][4];
    #pragma unroll
    for (int p = 0; p < 2; p++)
        #pragma unroll
        for (int q = 0; q < 2; q++)
            #pragma unroll
            for (int i = 0; i < 4; i++)
                #pragma unroll
                for (int j = 0; j < 4; j++) acc[p][q][i][j] = 0.f;

    const int NT = K >> 4;
    for (int kt = 0; kt < NT; kt++) {
        As[akv+0][ar]    = a0.x; As[akv+1][ar]    = a0.y;
        As[akv+2][ar]    = a0.z; As[akv+3][ar]    = a0.w;
        As[akv+0][ar+64] = a1.x; As[akv+1][ar+64] = a1.y;
        As[akv+2][ar+64] = a1.z; As[akv+3][ar+64] = a1.w;
        *(float4*)&Bs[bkr][bnv]     = b0;
        *(float4*)&Bs[bkr+8][bnv]   = b1;
        __syncthreads();

        if (kt + 1 < NT) {   // prefetch next tile into registers
            a0 = *(const float4*)(Ap0 + (kt+1)*16);
            a1 = *(const float4*)(Ap1 + (kt+1)*16);
            b0 = *(const float4*)(Bp0 + (size_t)(kt+1)*16*N);
            b1 = *(const float4*)(Bp1 + (size_t)(kt+1)*16*N);
        }

        #pragma unroll
        for (int k = 0; k < 16; k++) {
            float4 t0 = *(float4*)&As[k][ty*4];
            float4 t1 = *(float4*)&As[k][64 + ty*4];
            float4 t2 = *(float4*)&Bs[k][tx*4];
            float4 t3 = *(float4*)&Bs[k][64 + tx*4];
            float ra0[4] = {t0.x, t0.y, t0.z, t0.w};
            float ra1[4] = {t1.x, t1.y, t1.z, t1.w};
            float rb0[4] = {t2.x, t2.y, t2.z, t2.w};
            float rb1[4] = {t3.x, t3.y, t3.z, t3.w};
            #pragma unroll
            for (int i = 0; i < 4; i++)
                #pragma unroll
                for (int j = 0; j < 4; j++) {
                    acc[0][0][i][j] += ra0[i] * rb0[j];
                    acc[0][1][i][j] += ra0[i] * rb1[j];
                    acc[1][0][i][j] += ra1[i] * rb0[j];
                    acc[1][1][i][j] += ra1[i] * rb1[j];
                }
        }
        __syncthreads();
    }

    #pragma unroll
    for (int ri = 0; ri < 2; ri++)
        #pragma unroll
        for (int i = 0; i < 4; i++) {
            const int row = m0 + ri*64 + ty*4 + i;
            #pragma unroll
            for (int ci = 0; ci < 2; ci++) {
                const int cn = n0 + ci*64 + tx*4;
                float4 v;
                v.x = acc[ri][ci][i][0] + bias[cn+0];
                v.y = acc[ri][ci][i][1] + bias[cn+1];
                v.z = acc[ri][ci][i][2] + bias[cn+2];
                v.w = acc[ri][ci][i][3] + bias[cn+3];
                if (PERMUTE) {
                    // row = b*SEQ + t ; cn = h*HD + d  ->  [(b*NH+h)*SEQ + t][d]
                    const int bb = row >> 11;        // SEQ = 2048
                    const int t  = row & 2047;
                    const int h  = cn >> 6;          // HD = 64
                    const int d  = cn & 63;
                    size_t idx = ((size_t)(bb*NH + h) * SEQ + t) * HD + d;
                    *(float4*)&C[idx] = v;
                } else {
                    *(float4*)&C[(size_t)row * N + cn] = v;
                }
            }
        }
}

// Fused Q/K/V projection: blockIdx.z selects weight/bias/output.
// One launch of 3*256 CTAs instead of 3 launches of 256 -> one tail, not three.
__global__ void __launch_bounds__(256) qkv_proj_kernel(
    const float* __restrict__ A,
    const float* __restrict__ Wq, const float* __restrict__ bq, float* __restrict__ Cq,
    const float* __restrict__ Wk, const float* __restrict__ bk, float* __restrict__ Ck,
    const float* __restrict__ Wv, const float* __restrict__ bv, float* __restrict__ Cv)
{
    const float* W; const float* b; float* C;
    if (blockIdx.z == 0)      { W = Wq; b = bq; C = Cq; }
    else if (blockIdx.z == 1) { W = Wk; b = bk; C = Ck; }
    else                      { W = Wv; b = bv; C = Cv; }
    gemm_body<1>(A, W, b, C, MROWS, EMB, EMB,
                 blockIdx.y * 128, blockIdx.x * 128);
}

// Output projection: plain row-major GEMM.
__global__ void __launch_bounds__(256) out_proj_kernel(
    const float* __restrict__ A, const float* __restrict__ W,
    const float* __restrict__ bias, float* __restrict__ C)
{
    gemm_body<0>(A, W, bias, C, MROWS, EMB, EMB,
                 blockIdx.y * 128, blockIdx.x * 128);
}

// Causal flash attention, fp32. One CTA: (bh, 64-query tile). 256 thr, 4x4/thread.
__global__ void __launch_bounds__(256) flash_kernel(
    const float* __restrict__ Q, const float* __restrict__ K,
    const float* __restrict__ V, float* __restrict__ O)
{
    extern __shared__ float sm[];
    float* Qs = sm;              // [d][row]   64 x FS
    float* Ks = Qs + 64*FS;      // [d][col]
    float* Vs = Ks + 64*FS;      // [key][d]
    float* Ps = Vs + 64*FS;      // [row][key]

    const int tid = threadIdx.x;
    const int tx  = tid & 15;
    const int ty  = tid >> 4;
    const int bh  = blockIdx.x;
    const int qt  = (int)gridDim.y - 1 - (int)blockIdx.y;  // big tiles first
    const int q0  = qt * 64;

    const float* Qb = Q + (size_t)bh * SEQ * HD;
    const float* Kb = K + (size_t)bh * SEQ * HD;
    const float* Vb = V + (size_t)bh * SEQ * HD;

    const int lr = tid >> 4;          // 0..15 row within pass
    const int ld = (tid & 15) << 2;   // d base 0..60

    // Load Q tile transposed, fold 1/sqrt(64)
    #pragma unroll
    for (int p = 0; p < 4; p++) {
        int r = lr + p*16;
        float4 v = *(const float4*)&Qb[(size_t)(q0 + r)*HD + ld];
        Qs[(ld+0)*FS + r] = v.x * 0.125f;
        Qs[(ld+1)*FS + r] = v.y * 0.125f;
        Qs[(ld+2)*FS + r] = v.z * 0.125f;
        Qs[(ld+3)*FS + r] = v.w * 0.125f;
    }

    float m[4], l[4], acc[4][4];
    #pragma unroll
    for (int i = 0; i < 4; i++) {
        m[i] = -1e30f; l[i] = 0.f;
        #pragma unroll
        for (int j = 0; j < 4; j++) acc[i][j] = 0.f;
    }

    for (int kt = 0; kt <= qt; kt++) {
        const int k0 = kt * 64;
        #pragma unroll
        for (int p = 0; p < 4; p++) {
            int r = lr + p*16;
            float4 kv = *(const float4*)&Kb[(size_t)(k0 + r)*HD + ld];
            Ks[(ld+0)*FS + r] = kv.x;
            Ks[(ld+1)*FS + r] = kv.y;
            Ks[(ld+2)*FS + r] = kv.z;
            Ks[(ld+3)*FS + r] = kv.w;
            float4 vv = *(const float4*)&Vb[(size_t)(k0 + r)*HD + ld];
            *(float4*)&Vs[r*FS + ld] = vv;
        }
        __syncthreads();   // also covers Qs on first iteration

        float s[4][4];
        #pragma unroll
        for (int i = 0; i < 4; i++)
            #pragma unroll
            for (int j = 0; j < 4; j++) s[i][j] = 0.f;

        #pragma unroll 8
        for (int d = 0; d < 64; d++) {
            float4 qv = *(float4*)&Qs[d*FS + ty*4];
            float4 kv = *(float4*)&Ks[d*FS + tx*4];
            float qa[4] = {qv.x, qv.y, qv.z, qv.w};
            float ka[4] = {kv.x, kv.y, kv.z, kv.w};
            #pragma unroll
            for (int i = 0; i < 4; i++)
                #pragma unroll
                for (int j = 0; j < 4; j++) s[i][j] += qa[i] * ka[j];
        }

        if (kt == qt) {   // only diagonal tile needs the causal mask
            #pragma unroll
            for (int i = 0; i < 4; i++)
                #pragma unroll
                for (int j = 0; j < 4; j++)
                    if (tx*4 + j > ty*4 + i) s[i][j] = -1e30f;
        }

        #pragma unroll
        for (int i = 0; i < 4; i++) {
            float mt = fmaxf(fmaxf(s[i][0], s[i][1]), fmaxf(s[i][2], s[i][3]));
            #pragma unroll
            for (int o = 8; o >= 1; o >>= 1)
                mt = fmaxf(mt, __shfl_xor_sync(0xffffffffu, mt, o));
            const float mn   = fmaxf(m[i], mt);
            const float corr = __expf(m[i] - mn);
            float rs = 0.f;
            #pragma unroll
            for (int j = 0; j < 4; j++) {
                s[i][j] = __expf(s[i][j] - mn);
                rs += s[i][j];
            }
            #pragma unroll
            for (int o = 8; o >= 1; o >>= 1)
                rs += __shfl_xor_sync(0xffffffffu, rs, o);
            l[i] = l[i]*corr + rs;
            m[i] = mn;
            #pragma unroll
            for (int j = 0; j < 4; j++) acc[i][j] *= corr;
            *(float4*)&Ps[(ty*4+i)*FS + tx*4] =
                make_float4(s[i][0], s[i][1], s[i][2], s[i][3]);
        }
        __syncthreads();

        #pragma unroll 8
        for (int kk = 0; kk < 64; kk++) {
            float4 vv = *(float4*)&Vs[kk*FS + tx*4];
            float va[4] = {vv.x, vv.y, vv.z, vv.w};
            float p0 = Ps[(ty*4+0)*FS + kk];
            float p1 = Ps[(ty*4+1)*FS + kk];
            float p2 = Ps[(ty*4+2)*FS + kk];
            float p3 = Ps[(ty*4+3)*FS + kk];
            #pragma unroll
            for (int j = 0; j < 4; j++) {
                acc[0][j] += p0 * va[j];
                acc[1][j] += p1 * va[j];
                acc[2][j] += p2 * va[j];
                acc[3][j] += p3 * va[j];
            }
        }
        __syncthreads();
    }

    const int bb = bh >> 4;   // NH = 16
    const int h  = bh & 15;
    #pragma unroll
    for (int i = 0; i < 4; i++) {
        const float inv = 1.f / l[i];
        const int t = q0 + ty*4 + i;
        float4 o;
        o.x = acc[i][0] * inv;
        o.y = acc[i][1] * inv;
        o.z = acc[i][2] * inv;
        o.w = acc[i][3] * inv;
        *(float4*)&O[((size_t)(bb*SEQ + t))*EMB + h*HD + tx*4] = o;
    }
}

extern "C" void kernel_launch(void* const* d_in, const int* in_sizes, int n_in,
                              void* d_out, int out_size)
{
    const float* x  = (const float*)d_in[0];
    const float* Wq = (const float*)d_in[1];
    const float* bq = (const float*)d_in[2];
    const float* Wk = (const float*)d_in[3];
    const float* bk = (const float*)d_in[4];
    const float* Wv = (const float*)d_in[5];
    const float* bv = (const float*)d_in[6];
    const float* Wo = (const float*)d_in[7];
    const float* bo = (const float*)d_in[8];
    float* out = (float*)d_out;

    float *qb, *kb, *vb, *ob;
    cudaGetSymbolAddress((void**)&qb, g_Q);
    cudaGetSymbolAddress((void**)&kb, g_K);
    cudaGetSymbolAddress((void**)&vb, g_V);
    cudaGetSymbolAddress((void**)&ob, g_O);

    dim3 gqkv(EMB/128, MROWS/128, 3);   // (8, 32, 3) = 768 CTAs, one launch
    qkv_proj_kernel<<<gqkv, 256>>>(x, Wq, bq, qb, Wk, bk, kb, Wv, bv, vb);

    const int smem = 4 * 64 * FS * sizeof(float);   // 69632 B
    cudaFuncSetAttribute(flash_kernel,
                         cudaFuncAttributeMaxDynamicSharedMemorySize, smem);
    flash_kernel<<<dim3(BATCH*NH, SEQ/64), 256, smem>>>(qb, kb, vb, ob);

    out_proj_kernel<<<dim3(EMB/128, MROWS/128), 256>>>(ob, Wo, bo, out);
}

// round 7
// speedup vs baseline: 1.4488x; 1.4488x over previous
#include <cuda_runtime.h>
#include <math.h>
#include <stdint.h>

#define BATCH 2
#define SEQ   2048
#define EMB   1024
#define NH    16
#define HD    64
#define MROWS (BATCH*SEQ)   // 4096
#define FS    68            // padded smem row stride (floats) for flash tiles

// Scratch (allocation-free): Q,K,V in [B,H,T,D] packed as [(b*NH+h)*SEQ+t][HD];
// O (attention output) in [B,T,C] row-major.
__device__ float g_Q[MROWS*EMB];
__device__ float g_K[MROWS*EMB];
__device__ float g_V[MROWS*EMB];
__device__ float g_O[MROWS*EMB];

__device__ __forceinline__ float tf32r(float x) {
    uint32_t u;
    asm("cvt.rna.tf32.f32 %0, %1;" : "=r"(u) : "f"(x));
    return __uint_as_float(u);
}

__device__ __forceinline__ void mma_tf32(float d[4],
                                         const uint32_t a[4],
                                         const uint32_t b[2]) {
    asm volatile(
        "mma.sync.aligned.m16n8k8.row.col.f32.tf32.tf32.f32 "
        "{%0,%1,%2,%3}, {%4,%5,%6,%7}, {%8,%9}, {%0,%1,%2,%3};"
        : "+f"(d[0]), "+f"(d[1]), "+f"(d[2]), "+f"(d[3])
        : "r"(a[0]), "r"(a[1]), "r"(a[2]), "r"(a[3]),
          "r"(b[0]), "r"(b[1]));
}

// Tensor-core (tf32) GEMM body: C[M,N] = A @ W + bias, 128x128x16 tiles,
// 8 warps (2m x 4n), warp tile 64x32 via m16n8k8.
// PERMUTE=1 scatters output into [B,H,T,D].
template<int PERMUTE>
__device__ __forceinline__ void gemm_body(
    const float* __restrict__ A, const float* __restrict__ W,
    const float* __restrict__ bias, float* __restrict__ C,
    int M, int N, int K, int m0, int n0)
{
    __shared__ float As[128][20];   // [m][k], pad 4 -> conflict-free frag loads
    __shared__ float Bs[16][132];   // [k][n], pad 4

    const int tid    = threadIdx.x;
    const int lane   = tid & 31;
    const int g      = lane >> 2;     // 0..7
    const int c      = lane & 3;      // 0..3
    const int warpId = tid >> 5;
    const int wm     = warpId >> 2;   // 0..1
    const int wn     = warpId & 3;    // 0..3

    // gmem load assignments (same as fp32 version)
    const int ar  = tid >> 2;          // 0..63 (row), second half +64
    const int akv = (tid & 3) << 2;    // k base 0,4,8,12
    const int bkr = tid >> 5;          // 0..7 (k row), second +8
    const int bnv = (tid & 31) << 2;   // n base 0..124

    const float* Ap0 = A + (size_t)(m0 + ar) * K + akv;
    const float* Ap1 = Ap0 + (size_t)64 * K;
    const float* Bp0 = W + (size_t)bkr * N + n0 + bnv;
    const float* Bp1 = Bp0 + (size_t)8 * N;

    float4 a0 = *(const float4*)Ap0;
    float4 a1 = *(const float4*)Ap1;
    float4 b0 = *(const float4*)Bp0;
    float4 b1 = *(const float4*)Bp1;

    float acc[4][4][4];
    #pragma unroll
    for (int mt = 0; mt < 4; mt++)
        #pragma unroll
        for (int nt = 0; nt < 4; nt++)
            #pragma unroll
            for (int e = 0; e < 4; e++) acc[mt][nt][e] = 0.f;

    const int NT = K >> 4;
    for (int kt = 0; kt < NT; kt++) {
        // store to smem with tf32 rounding
        As[ar][akv+0]    = tf32r(a0.x); As[ar][akv+1]    = tf32r(a0.y);
        As[ar][akv+2]    = tf32r(a0.z); As[ar][akv+3]    = tf32r(a0.w);
        As[ar+64][akv+0] = tf32r(a1.x); As[ar+64][akv+1] = tf32r(a1.y);
        As[ar+64][akv+2] = tf32r(a1.z); As[ar+64][akv+3] = tf32r(a1.w);
        float4 tb0 = make_float4(tf32r(b0.x), tf32r(b0.y), tf32r(b0.z), tf32r(b0.w));
        float4 tb1 = make_float4(tf32r(b1.x), tf32r(b1.y), tf32r(b1.z), tf32r(b1.w));
        *(float4*)&Bs[bkr][bnv]   = tb0;
        *(float4*)&Bs[bkr+8][bnv] = tb1;
        __syncthreads();

        if (kt + 1 < NT) {   // prefetch next tile
            a0 = *(const float4*)(Ap0 + (kt+1)*16);
            a1 = *(const float4*)(Ap1 + (kt+1)*16);
            b0 = *(const float4*)(Bp0 + (size_t)(kt+1)*16*N);
            b1 = *(const float4*)(Bp1 + (size_t)(kt+1)*16*N);
        }

        #pragma unroll
        for (int kk = 0; kk < 16; kk += 8) {
            uint32_t af[4][4];
            #pragma unroll
            for (int mt = 0; mt < 4; mt++) {
                const int r = wm*64 + mt*16 + g;
                af[mt][0] = __float_as_uint(As[r  ][kk + c]);
                af[mt][1] = __float_as_uint(As[r+8][kk + c]);
                af[mt][2] = __float_as_uint(As[r  ][kk + c + 4]);
                af[mt][3] = __float_as_uint(As[r+8][kk + c + 4]);
            }
            uint32_t bf[4][2];
            #pragma unroll
            for (int nt = 0; nt < 4; nt++) {
                const int n = wn*32 + nt*8 + g;
                bf[nt][0] = __float_as_uint(Bs[kk + c    ][n]);
                bf[nt][1] = __float_as_uint(Bs[kk + c + 4][n]);
            }
            #pragma unroll
            for (int mt = 0; mt < 4; mt++)
                #pragma unroll
                for (int nt = 0; nt < 4; nt++)
                    mma_tf32(acc[mt][nt], af[mt], bf[nt]);
        }
        __syncthreads();
    }

    // epilogue: c0,c1 -> (row g, cols 2c,2c+1); c2,c3 -> (row g+8)
    #pragma unroll
    for (int nt = 0; nt < 4; nt++) {
        const int col = n0 + wn*32 + nt*8 + 2*c;
        const float bx = bias[col];
        const float by = bias[col+1];
        #pragma unroll
        for (int mt = 0; mt < 4; mt++) {
            const int r0 = m0 + wm*64 + mt*16 + g;
            float2 v0 = make_float2(acc[mt][nt][0] + bx, acc[mt][nt][1] + by);
            float2 v1 = make_float2(acc[mt][nt][2] + bx, acc[mt][nt][3] + by);
            if (PERMUTE) {
                const int h = col >> 6;          // HD = 64
                const int d = col & 63;
                {
                    const int bb = r0 >> 11;     // SEQ = 2048
                    const int t  = r0 & 2047;
                    *(float2*)&C[((size_t)(bb*NH + h) * SEQ + t) * HD + d] = v0;
                }
                {
                    const int r1 = r0 + 8;
                    const int bb = r1 >> 11;
                    const int t  = r1 & 2047;
                    *(float2*)&C[((size_t)(bb*NH + h) * SEQ + t) * HD + d] = v1;
                }
            } else {
                *(float2*)&C[(size_t)r0 * N + col]       = v0;
                *(float2*)&C[(size_t)(r0+8) * N + col]   = v1;
            }
        }
    }
}

// Fused Q/K/V projection: blockIdx.z selects weight/bias/output.
__global__ void __launch_bounds__(256) qkv_proj_kernel(
    const float* __restrict__ A,
    const float* __restrict__ Wq, const float* __restrict__ bq, float* __restrict__ Cq,
    const float* __restrict__ Wk, const float* __restrict__ bk, float* __restrict__ Ck,
    const float* __restrict__ Wv, const float* __restrict__ bv, float* __restrict__ Cv)
{
    const float* W; const float* b; float* C;
    if (blockIdx.z == 0)      { W = Wq; b = bq; C = Cq; }
    else if (blockIdx.z == 1) { W = Wk; b = bk; C = Ck; }
    else                      { W = Wv; b = bv; C = Cv; }
    gemm_body<1>(A, W, b, C, MROWS, EMB, EMB,
                 blockIdx.y * 128, blockIdx.x * 128);
}

// Output projection: plain row-major GEMM.
__global__ void __launch_bounds__(256) out_proj_kernel(
    const float* __restrict__ A, const float* __restrict__ W,
    const float* __restrict__ bias, float* __restrict__ C)
{
    gemm_body<0>(A, W, bias, C, MROWS, EMB, EMB,
                 blockIdx.y * 128, blockIdx.x * 128);
}

// Causal flash attention, fp32. One CTA: (bh, 64-query tile). 256 thr, 4x4/thread.
__global__ void __launch_bounds__(256) flash_kernel(
    const float* __restrict__ Q, const float* __restrict__ K,
    const float* __restrict__ V, float* __restrict__ O)
{
    extern __shared__ float sm[];
    float* Qs = sm;              // [d][row]   64 x FS
    float* Ks = Qs + 64*FS;      // [d][col]
    float* Vs = Ks + 64*FS;      // [key][d]
    float* Ps = Vs + 64*FS;      // [row][key]

    const int tid = threadIdx.x;
    const int tx  = tid & 15;
    const int ty  = tid >> 4;
    const int bh  = blockIdx.x;
    const int qt  = (int)gridDim.y - 1 - (int)blockIdx.y;  // big tiles first
    const int q0  = qt * 64;

    const float* Qb = Q + (size_t)bh * SEQ * HD;
    const float* Kb = K + (size_t)bh * SEQ * HD;
    const float* Vb = V + (size_t)bh * SEQ * HD;

    const int lr = tid >> 4;          // 0..15 row within pass
    const int ld = (tid & 15) << 2;   // d base 0..60

    // Load Q tile transposed, fold 1/sqrt(64)
    #pragma unroll
    for (int p = 0; p < 4; p++) {
        int r = lr + p*16;
        float4 v = *(const float4*)&Qb[(size_t)(q0 + r)*HD + ld];
        Qs[(ld+0)*FS + r] = v.x * 0.125f;
        Qs[(ld+1)*FS + r] = v.y * 0.125f;
        Qs[(ld+2)*FS + r] = v.z * 0.125f;
        Qs[(ld+3)*FS + r] = v.w * 0.125f;
    }

    float m[4], l[4], acc[4][4];
    #pragma unroll
    for (int i = 0; i < 4; i++) {
        m[i] = -1e30f; l[i] = 0.f;
        #pragma unroll
        for (int j = 0; j < 4; j++) acc[i][j] = 0.f;
    }

    for (int kt = 0; kt <= qt; kt++) {
        const int k0 = kt * 64;
        #pragma unroll
        for (int p = 0; p < 4; p++) {
            int r = lr + p*16;
            float4 kv = *(const float4*)&Kb[(size_t)(k0 + r)*HD + ld];
            Ks[(ld+0)*FS + r] = kv.x;
            Ks[(ld+1)*FS + r] = kv.y;
            Ks[(ld+2)*FS + r] = kv.z;
            Ks[(ld+3)*FS + r] = kv.w;
            float4 vv = *(const float4*)&Vb[(size_t)(k0 + r)*HD + ld];
            *(float4*)&Vs[r*FS + ld] = vv;
        }
        __syncthreads();   // also covers Qs on first iteration

        float s[4][4];
        #pragma unroll
        for (int i = 0; i < 4; i++)
            #pragma unroll
            for (int j = 0; j < 4; j++) s[i][j] = 0.f;

        #pragma unroll 8
        for (int d = 0; d < 64; d++) {
            float4 qv = *(float4*)&Qs[d*FS + ty*4];
            float4 kv = *(float4*)&Ks[d*FS + tx*4];
            float qa[4] = {qv.x, qv.y, qv.z, qv.w};
            float ka[4] = {kv.x, kv.y, kv.z, kv.w};
            #pragma unroll
            for (int i = 0; i < 4; i++)
                #pragma unroll
                for (int j = 0; j < 4; j++) s[i][j] += qa[i] * ka[j];
        }

        if (kt == qt) {   // only diagonal tile needs the causal mask
            #pragma unroll
            for (int i = 0; i < 4; i++)
                #pragma unroll
                for (int j = 0; j < 4; j++)
                    if (tx*4 + j > ty*4 + i) s[i][j] = -1e30f;
        }

        #pragma unroll
        for (int i = 0; i < 4; i++) {
            float mt = fmaxf(fmaxf(s[i][0], s[i][1]), fmaxf(s[i][2], s[i][3]));
            #pragma unroll
            for (int o = 8; o >= 1; o >>= 1)
                mt = fmaxf(mt, __shfl_xor_sync(0xffffffffu, mt, o));
            const float mn   = fmaxf(m[i], mt);
            const float corr = __expf(m[i] - mn);
            float rs = 0.f;
            #pragma unroll
            for (int j = 0; j < 4; j++) {
                s[i][j] = __expf(s[i][j] - mn);
                rs += s[i][j];
            }
            #pragma unroll
            for (int o = 8; o >= 1; o >>= 1)
                rs += __shfl_xor_sync(0xffffffffu, rs, o);
            l[i] = l[i]*corr + rs;
            m[i] = mn;
            #pragma unroll
            for (int j = 0; j < 4; j++) acc[i][j] *= corr;
            *(float4*)&Ps[(ty*4+i)*FS + tx*4] =
                make_float4(s[i][0], s[i][1], s[i][2], s[i][3]);
        }
        __syncthreads();

        #pragma unroll 8
        for (int kk = 0; kk < 64; kk++) {
            float4 vv = *(float4*)&Vs[kk*FS + tx*4];
            float va[4] = {vv.x, vv.y, vv.z, vv.w};
            float p0 = Ps[(ty*4+0)*FS + kk];
            float p1 = Ps[(ty*4+1)*FS + kk];
            float p2 = Ps[(ty*4+2)*FS + kk];
            float p3 = Ps[(ty*4+3)*FS + kk];
            #pragma unroll
            for (int j = 0; j < 4; j++) {
                acc[0][j] += p0 * va[j];
                acc[1][j] += p1 * va[j];
                acc[2][j] += p2 * va[j];
                acc[3][j] += p3 * va[j];
            }
        }
        __syncthreads();
    }

    const int bb = bh >> 4;   // NH = 16
    const int h  = bh & 15;
    #pragma unroll
    for (int i = 0; i < 4; i++) {
        const float inv = 1.f / l[i];
        const int t = q0 + ty*4 + i;
        float4 o;
        o.x = acc[i][0] * inv;
        o.y = acc[i][1] * inv;
        o.z = acc[i][2] * inv;
        o.w = acc[i][3] * inv;
        *(float4*)&O[((size_t)(bb*SEQ + t))*EMB + h*HD + tx*4] = o;
    }
}

extern "C" void kernel_launch(void* const* d_in, const int* in_sizes, int n_in,
                              void* d_out, int out_size)
{
    const float* x  = (const float*)d_in[0];
    const float* Wq = (const float*)d_in[1];
    const float* bq = (const float*)d_in[2];
    const float* Wk = (const float*)d_in[3];
    const float* bk = (const float*)d_in[4];
    const float* Wv = (const float*)d_in[5];
    const float* bv = (const float*)d_in[6];
    const float* Wo = (const float*)d_in[7];
    const float* bo = (const float*)d_in[8];
    float* out = (float*)d_out;

    float *qb, *kb, *vb, *ob;
    cudaGetSymbolAddress((void**)&qb, g_Q);
    cudaGetSymbolAddress((void**)&kb, g_K);
    cudaGetSymbolAddress((void**)&vb, g_V);
    cudaGetSymbolAddress((void**)&ob, g_O);

    dim3 gqkv(EMB/128, MROWS/128, 3);   // (8, 32, 3) = 768 CTAs, one launch
    qkv_proj_kernel<<<gqkv, 256>>>(x, Wq, bq, qb, Wk, bk, kb, Wv, bv, vb);

    const int smem = 4 * 64 * FS * sizeof(float);   // 69632 B
    cudaFuncSetAttribute(flash_kernel,
                         cudaFuncAttributeMaxDynamicSharedMemorySize, smem);
    flash_kernel<<<dim3(BATCH*NH, SEQ/64), 256, smem>>>(qb, kb, vb, ob);

    out_proj_kernel<<<dim3(EMB/128, MROWS/128), 256>>>(ob, Wo, bo, out);
}

// round 9
// speedup vs baseline: 1.6674x; 1.1509x over previous
#include <cuda_runtime.h>
#include <math.h>
#include <stdint.h>

#define BATCH 2
#define SEQ   2048
#define EMB   1024
#define NH    16
#define HD    64
#define MROWS (BATCH*SEQ)   // 4096

// flash tiling
#define QT 128
#define KT 64
#define QSS 68   // Qs stride
#define KSS 68   // Ks stride
#define VSS 72   // Vs stride
#define PSS 68   // Ps stride

// Scratch (allocation-free): Q,K,V in [B,H,T,D] packed as [(b*NH+h)*SEQ+t][HD];
// O (attention output) in [B,T,C] row-major.
__device__ float g_Q[MROWS*EMB];
__device__ float g_K[MROWS*EMB];
__device__ float g_V[MROWS*EMB];
__device__ float g_O[MROWS*EMB];

__device__ __forceinline__ float tf32r(float x) {
    uint32_t u;
    asm("cvt.rna.tf32.f32 %0, %1;" : "=r"(u) : "f"(x));
    return __uint_as_float(u);
}

__device__ __forceinline__ void mma_tf32(float d[4],
                                         const uint32_t a[4],
                                         const uint32_t b[2]) {
    asm volatile(
        "mma.sync.aligned.m16n8k8.row.col.f32.tf32.tf32.f32 "
        "{%0,%1,%2,%3}, {%4,%5,%6,%7}, {%8,%9}, {%0,%1,%2,%3};"
        : "+f"(d[0]), "+f"(d[1]), "+f"(d[2]), "+f"(d[3])
        : "r"(a[0]), "r"(a[1]), "r"(a[2]), "r"(a[3]),
          "r"(b[0]), "r"(b[1]));
}

// Tensor-core (tf32) GEMM body: C[M,N] = A @ W + bias, 128x128x16 tiles,
// 8 warps (2m x 4n), warp tile 64x32 via m16n8k8.
// PERMUTE=1 scatters output into [B,H,T,D].
template<int PERMUTE>
__device__ __forceinline__ void gemm_body(
    const float* __restrict__ A, const float* __restrict__ W,
    const float* __restrict__ bias, float* __restrict__ C,
    int M, int N, int K, int m0, int n0)
{
    __shared__ float As[128][20];   // [m][k], pad 4 -> conflict-free frag loads
    __shared__ float Bs[16][132];   // [k][n], pad 4

    const int tid    = threadIdx.x;
    const int lane   = tid & 31;
    const int g      = lane >> 2;     // 0..7
    const int c      = lane & 3;      // 0..3
    const int warpId = tid >> 5;
    const int wm     = warpId >> 2;   // 0..1
    const int wn     = warpId & 3;    // 0..3

    const int ar  = tid >> 2;          // 0..63 (row), second half +64
    const int akv = (tid & 3) << 2;    // k base 0,4,8,12
    const int bkr = tid >> 5;          // 0..7 (k row), second +8
    const int bnv = (tid & 31) << 2;   // n base 0..124

    const float* Ap0 = A + (size_t)(m0 + ar) * K + akv;
    const float* Ap1 = Ap0 + (size_t)64 * K;
    const float* Bp0 = W + (size_t)bkr * N + n0 + bnv;
    const float* Bp1 = Bp0 + (size_t)8 * N;

    float4 a0 = *(const float4*)Ap0;
    float4 a1 = *(const float4*)Ap1;
    float4 b0 = *(const float4*)Bp0;
    float4 b1 = *(const float4*)Bp1;

    float acc[4][4][4];
    #pragma unroll
    for (int mt = 0; mt < 4; mt++)
        #pragma unroll
        for (int nt = 0; nt < 4; nt++)
            #pragma unroll
            for (int e = 0; e < 4; e++) acc[mt][nt][e] = 0.f;

    const int NT = K >> 4;
    for (int kt = 0; kt < NT; kt++) {
        As[ar][akv+0]    = tf32r(a0.x); As[ar][akv+1]    = tf32r(a0.y);
        As[ar][akv+2]    = tf32r(a0.z); As[ar][akv+3]    = tf32r(a0.w);
        As[ar+64][akv+0] = tf32r(a1.x); As[ar+64][akv+1] = tf32r(a1.y);
        As[ar+64][akv+2] = tf32r(a1.z); As[ar+64][akv+3] = tf32r(a1.w);
        float4 tb0 = make_float4(tf32r(b0.x), tf32r(b0.y), tf32r(b0.z), tf32r(b0.w));
        float4 tb1 = make_float4(tf32r(b1.x), tf32r(b1.y), tf32r(b1.z), tf32r(b1.w));
        *(float4*)&Bs[bkr][bnv]   = tb0;
        *(float4*)&Bs[bkr+8][bnv] = tb1;
        __syncthreads();

        if (kt + 1 < NT) {
            a0 = *(const float4*)(Ap0 + (kt+1)*16);
            a1 = *(const float4*)(Ap1 + (kt+1)*16);
            b0 = *(const float4*)(Bp0 + (size_t)(kt+1)*16*N);
            b1 = *(const float4*)(Bp1 + (size_t)(kt+1)*16*N);
        }

        #pragma unroll
        for (int kk = 0; kk < 16; kk += 8) {
            uint32_t af[4][4];
            #pragma unroll
            for (int mt = 0; mt < 4; mt++) {
                const int r = wm*64 + mt*16 + g;
                af[mt][0] = __float_as_uint(As[r  ][kk + c]);
                af[mt][1] = __float_as_uint(As[r+8][kk + c]);
                af[mt][2] = __float_as_uint(As[r  ][kk + c + 4]);
                af[mt][3] = __float_as_uint(As[r+8][kk + c + 4]);
            }
            uint32_t bf[4][2];
            #pragma unroll
            for (int nt = 0; nt < 4; nt++) {
                const int n = wn*32 + nt*8 + g;
                bf[nt][0] = __float_as_uint(Bs[kk + c    ][n]);
                bf[nt][1] = __float_as_uint(Bs[kk + c + 4][n]);
            }
            #pragma unroll
            for (int mt = 0; mt < 4; mt++)
                #pragma unroll
                for (int nt = 0; nt < 4; nt++)
                    mma_tf32(acc[mt][nt], af[mt], bf[nt]);
        }
        __syncthreads();
    }

    #pragma unroll
    for (int nt = 0; nt < 4; nt++) {
        const int col = n0 + wn*32 + nt*8 + 2*c;
        const float bx = bias[col];
        const float by = bias[col+1];
        #pragma unroll
        for (int mt = 0; mt < 4; mt++) {
            const int r0 = m0 + wm*64 + mt*16 + g;
            float2 v0 = make_float2(acc[mt][nt][0] + bx, acc[mt][nt][1] + by);
            float2 v1 = make_float2(acc[mt][nt][2] + bx, acc[mt][nt][3] + by);
            if (PERMUTE) {
                const int h = col >> 6;          // HD = 64
                const int d = col & 63;
                {
                    const int bb = r0 >> 11;     // SEQ = 2048
                    const int t  = r0 & 2047;
                    *(float2*)&C[((size_t)(bb*NH + h) * SEQ + t) * HD + d] = v0;
                }
                {
                    const int r1 = r0 + 8;
                    const int bb = r1 >> 11;
                    const int t  = r1 & 2047;
                    *(float2*)&C[((size_t)(bb*NH + h) * SEQ + t) * HD + d] = v1;
                }
            } else {
                *(float2*)&C[(size_t)r0 * N + col]       = v0;
                *(float2*)&C[(size_t)(r0+8) * N + col]   = v1;
            }
        }
    }
}

__global__ void __launch_bounds__(256) qkv_proj_kernel(
    const float* __restrict__ A,
    const float* __restrict__ Wq, const float* __restrict__ bq, float* __restrict__ Cq,
    const float* __restrict__ Wk, const float* __restrict__ bk, float* __restrict__ Ck,
    const float* __restrict__ Wv, const float* __restrict__ bv, float* __restrict__ Cv)
{
    const float* W; const float* b; float* C;
    if (blockIdx.z == 0)      { W = Wq; b = bq; C = Cq; }
    else if (blockIdx.z == 1) { W = Wk; b = bk; C = Ck; }
    else                      { W = Wv; b = bv; C = Cv; }
    gemm_body<1>(A, W, b, C, MROWS, EMB, EMB,
                 blockIdx.y * 128, blockIdx.x * 128);
}

__global__ void __launch_bounds__(256) out_proj_kernel(
    const float* __restrict__ A, const float* __restrict__ W,
    const float* __restrict__ bias, float* __restrict__ C)
{
    gemm_body<0>(A, W, bias, C, MROWS, EMB, EMB,
                 blockIdx.y * 128, blockIdx.x * 128);
}

// Causal flash attention on the tensor pipe (tf32 mma, fp32 softmax state).
// CTA: 128 queries (8 warps x 16 rows), key tile 64. One CTA per (bh, qb).
__global__ void __launch_bounds__(256, 2) flash_kernel(
    const float* __restrict__ Q, const float* __restrict__ K,
    const float* __restrict__ V, float* __restrict__ O)
{
    extern __shared__ float sm[];
    float* Qs = sm;                 // [QT][QSS]  [row][d]
    float* Ks = Qs + QT*QSS;        // [KT][KSS]  [key][d]
    float* Vs = Ks + KT*KSS;        // [KT][VSS]  [key][d]
    float* Ps = Vs + KT*VSS;        // [QT][PSS]  [row][key]

    const int tid  = threadIdx.x;
    const int lane = tid & 31;
    const int w    = tid >> 5;       // warp 0..7 -> rows 16w..16w+15
    const int g    = lane >> 2;      // 0..7
    const int c    = lane & 3;       // 0..3
    const int bh   = blockIdx.x;
    const int qb   = (int)gridDim.y - 1 - (int)blockIdx.y;  // big tiles first
    const int q0   = qb * QT;

    const float* Qb = Q + (size_t)bh * SEQ * HD;
    const float* Kb = K + (size_t)bh * SEQ * HD;
    const float* Vb = V + (size_t)bh * SEQ * HD;

    const int lr = tid >> 4;          // 0..15
    const int ld = (tid & 15) << 2;   // 0..60

    // Load Q tile [QT][HD], fold 1/sqrt(64)=0.125, tf32-round.
    #pragma unroll
    for (int p = 0; p < 8; p++) {
        const int r = lr + p*16;
        float4 v = *(const float4*)&Qb[(size_t)(q0 + r)*HD + ld];
        Qs[r*QSS + ld+0] = tf32r(v.x * 0.125f);
        Qs[r*QSS + ld+1] = tf32r(v.y * 0.125f);
        Qs[r*QSS + ld+2] = tf32r(v.z * 0.125f);
        Qs[r*QSS + ld+3] = tf32r(v.w * 0.125f);
    }

    float m_lo = -1e30f, m_hi = -1e30f, l_lo = 0.f, l_hi = 0.f;
    float o[8][4];
    #pragma unroll
    for (int nt = 0; nt < 8; nt++)
        #pragma unroll
        for (int e = 0; e < 4; e++) o[nt][e] = 0.f;

    const int row_lo = q0 + 16*w + g;
    const int row_hi = row_lo + 8;
    const int ktn = 2*qb + 2;   // key tiles covering keys 0 .. q0+QT-1

    for (int kt = 0; kt < ktn; kt++) {
        const int k0 = kt * KT;
        // Load K,V tiles [KT][HD], tf32-round.
        #pragma unroll
        for (int p = 0; p < 4; p++) {
            const int r = lr + p*16;
            float4 kv = *(const float4*)&Kb[(size_t)(k0 + r)*HD + ld];
            Ks[r*KSS + ld+0] = tf32r(kv.x);
            Ks[r*KSS + ld+1] = tf32r(kv.y);
            Ks[r*KSS + ld+2] = tf32r(kv.z);
            Ks[r*KSS + ld+3] = tf32r(kv.w);
            float4 vv = *(const float4*)&Vb[(size_t)(k0 + r)*HD + ld];
            Vs[r*VSS + ld+0] = tf32r(vv.x);
            Vs[r*VSS + ld+1] = tf32r(vv.y);
            Vs[r*VSS + ld+2] = tf32r(vv.z);
            Vs[r*VSS + ld+3] = tf32r(vv.w);
        }
        __syncthreads();   // K/V (and first-iter Q) visible

        // ---- S = Q K^T : warp rows 16w..16w+15, all 64 keys ----
        float s[8][4];
        #pragma unroll
        for (int nt = 0; nt < 8; nt++)
            #pragma unroll
            for (int e = 0; e < 4; e++) s[nt][e] = 0.f;

        #pragma unroll
        for (int kd = 0; kd < 8; kd++) {
            uint32_t a[4];
            const int qr = (16*w + g)*QSS + kd*8;
            a[0] = __float_as_uint(Qs[qr + c]);
            a[1] = __float_as_uint(Qs[qr + 8*QSS + c]);
            a[2] = __float_as_uint(Qs[qr + c + 4]);
            a[3] = __float_as_uint(Qs[qr + 8*QSS + c + 4]);
            #pragma unroll
            for (int nt = 0; nt < 8; nt++) {
                uint32_t b[2];
                const int krr = (nt*8 + g)*KSS + kd*8;
                b[0] = __float_as_uint(Ks[krr + c]);
                b[1] = __float_as_uint(Ks[krr + c + 4]);
                mma_tf32(s[nt], a, b);
            }
        }

        // ---- causal mask (only last two tiles can overlap the diagonal) ----
        if (kt >= 2*qb) {
            #pragma unroll
            for (int nt = 0; nt < 8; nt++) {
                const int col = k0 + nt*8 + 2*c;
                if (col   > row_lo) s[nt][0] = -1e30f;
                if (col+1 > row_lo) s[nt][1] = -1e30f;
                if (col   > row_hi) s[nt][2] = -1e30f;
                if (col+1 > row_hi) s[nt][3] = -1e30f;
            }
        }

        // ---- online softmax over fragments (rows owned by 4-lane quads) ----
        float tmx_lo = -1e30f, tmx_hi = -1e30f;
        #pragma unroll
        for (int nt = 0; nt < 8; nt++) {
            tmx_lo = fmaxf(tmx_lo, fmaxf(s[nt][0], s[nt][1]));
            tmx_hi = fmaxf(tmx_hi, fmaxf(s[nt][2], s[nt][3]));
        }
        #pragma unroll
        for (int ox = 1; ox <= 2; ox <<= 1) {
            tmx_lo = fmaxf(tmx_lo, __shfl_xor_sync(0xffffffffu, tmx_lo, ox));
            tmx_hi = fmaxf(tmx_hi, __shfl_xor_sync(0xffffffffu, tmx_hi, ox));
        }
        const float mn_lo = fmaxf(m_lo, tmx_lo);
        const float mn_hi = fmaxf(m_hi, tmx_hi);
        const float cr_lo = __expf(m_lo - mn_lo);
        const float cr_hi = __expf(m_hi - mn_hi);
        m_lo = mn_lo; m_hi = mn_hi;

        float rs_lo = 0.f, rs_hi = 0.f;
        #pragma unroll
        for (int nt = 0; nt < 8; nt++) {
            float p0 = __expf(s[nt][0] - mn_lo);
            float p1 = __expf(s[nt][1] - mn_lo);
            float p2 = __expf(s[nt][2] - mn_hi);
            float p3 = __expf(s[nt][3] - mn_hi);
            rs_lo += p0 + p1;
            rs_hi += p2 + p3;
            const int pc = nt*8 + 2*c;
            *(float2*)&Ps[(16*w + g    )*PSS + pc] = make_float2(tf32r(p0), tf32r(p1));
            *(float2*)&Ps[(16*w + g + 8)*PSS + pc] = make_float2(tf32r(p2), tf32r(p3));
        }
        #pragma unroll
        for (int ox = 1; ox <= 2; ox <<= 1) {
            rs_lo += __shfl_xor_sync(0xffffffffu, rs_lo, ox);
            rs_hi += __shfl_xor_sync(0xffffffffu, rs_hi, ox);
        }
        l_lo = l_lo*cr_lo + rs_lo;
        l_hi = l_hi*cr_hi + rs_hi;
        #pragma unroll
        for (int nt = 0; nt < 8; nt++) {
            o[nt][0] *= cr_lo; o[nt][1] *= cr_lo;
            o[nt][2] *= cr_hi; o[nt][3] *= cr_hi;
        }
        __syncwarp();   // Ps rows are warp-private; warp-level fence suffices

        // ---- O += P V ----
        #pragma unroll
        for (int kd = 0; kd < 8; kd++) {
            uint32_t a[4];
            const int pr = (16*w + g)*PSS + kd*8;
            a[0] = __float_as_uint(Ps[pr + c]);
            a[1] = __float_as_uint(Ps[pr + 8*PSS + c]);
            a[2] = __float_as_uint(Ps[pr + c + 4]);
            a[3] = __float_as_uint(Ps[pr + 8*PSS + c + 4]);
            #pragma unroll
            for (int nt = 0; nt < 8; nt++) {
                uint32_t b[2];
                const int vr = (kd*8 + c)*VSS + nt*8 + g;
                b[0] = __float_as_uint(Vs[vr]);
                b[1] = __float_as_uint(Vs[vr + 4*VSS]);
                mma_tf32(o[nt], a, b);
            }
        }
        __syncthreads();   // all warps done with Ks/Vs before next tile load
    }

    // ---- epilogue: normalize and write [B,T,C] ----
    const float inv_lo = 1.f / l_lo;
    const float inv_hi = 1.f / l_hi;
    const int bb = bh >> 4;   // NH = 16
    const int h  = bh & 15;
    #pragma unroll
    for (int nt = 0; nt < 8; nt++) {
        const int col = h*HD + nt*8 + 2*c;
        *(float2*)&O[((size_t)(bb*SEQ + row_lo))*EMB + col] =
            make_float2(o[nt][0]*inv_lo, o[nt][1]*inv_lo);
        *(float2*)&O[((size_t)(bb*SEQ + row_hi))*EMB + col] =
            make_float2(o[nt][2]*inv_hi, o[nt][3]*inv_hi);
    }
}

extern "C" void kernel_launch(void* const* d_in, const int* in_sizes, int n_in,
                              void* d_out, int out_size)
{
    const float* x  = (const float*)d_in[0];
    const float* Wq = (const float*)d_in[1];
    const float* bq = (const float*)d_in[2];
    const float* Wk = (const float*)d_in[3];
    const float* bk = (const float*)d_in[4];
    const float* Wv = (const float*)d_in[5];
    const float* bv = (const float*)d_in[6];
    const float* Wo = (const float*)d_in[7];
    const float* bo = (const float*)d_in[8];
    float* out = (float*)d_out;

    float *qb, *kb, *vb, *ob;
    cudaGetSymbolAddress((void**)&qb, g_Q);
    cudaGetSymbolAddress((void**)&kb, g_K);
    cudaGetSymbolAddress((void**)&vb, g_V);
    cudaGetSymbolAddress((void**)&ob, g_O);

    dim3 gqkv(EMB/128, MROWS/128, 3);   // 768 CTAs, one launch
    qkv_proj_kernel<<<gqkv, 256>>>(x, Wq, bq, qb, Wk, bk, kb, Wv, bv, vb);

    const int smem = (QT*QSS + KT*KSS + KT*VSS + QT*PSS) * (int)sizeof(float); // 105472 B
    cudaFuncSetAttribute(flash_kernel,
                         cudaFuncAttributeMaxDynamicSharedMemorySize, smem);
    flash_kernel<<<dim3(BATCH*NH, SEQ/QT), 256, smem>>>(qb, kb, vb, ob);

    out_proj_kernel<<<dim3(EMB/128, MROWS/128), 256>>>(ob, Wo, bo, out);
}

// round 10
// speedup vs baseline: 2.7536x; 1.6514x over previous
#include <cuda_runtime.h>
#include <math.h>
#include <stdint.h>

#define BATCH 2
#define SEQ   2048
#define EMB   1024
#define NH    16
#define HD    64
#define MROWS (BATCH*SEQ)   // 4096

// flash tiling
#define QT 128
#define KT 64
#define QSS 68   // Qs stride
#define KSS 68   // Ks stride
#define VSS 72   // Vs stride
#define PSS 68   // Ps stride

// Scratch (allocation-free): Q,K,V in [B,H,T,D] packed as [(b*NH+h)*SEQ+t][HD];
// O (attention output) in [B,T,C] row-major.
__device__ float g_Q[MROWS*EMB];
__device__ float g_K[MROWS*EMB];
__device__ float g_V[MROWS*EMB];
__device__ float g_O[MROWS*EMB];

__device__ __forceinline__ float tf32r(float x) {
    uint32_t u;
    asm("cvt.rna.tf32.f32 %0, %1;" : "=r"(u) : "f"(x));
    return __uint_as_float(u);
}

__device__ __forceinline__ void mma_tf32(float d[4],
                                         const uint32_t a[4],
                                         const uint32_t b[2]) {
    asm volatile(
        "mma.sync.aligned.m16n8k8.row.col.f32.tf32.tf32.f32 "
        "{%0,%1,%2,%3}, {%4,%5,%6,%7}, {%8,%9}, {%0,%1,%2,%3};"
        : "+f"(d[0]), "+f"(d[1]), "+f"(d[2]), "+f"(d[3])
        : "r"(a[0]), "r"(a[1]), "r"(a[2]), "r"(a[3]),
          "r"(b[0]), "r"(b[1]));
}

// Tensor-core (tf32) GEMM body: C[M,N] = A @ W + bias, 128x128x16 tiles,
// 8 warps (2m x 4n), warp tile 64x32 via m16n8k8.
// Double-buffered smem: one __syncthreads per k-tile, LDG/STS overlap mma.
// PERMUTE=1 scatters output into [B,H,T,D].
template<int PERMUTE>
__device__ __forceinline__ void gemm_body(
    const float* __restrict__ A, const float* __restrict__ W,
    const float* __restrict__ bias, float* __restrict__ C,
    int M, int N, int K, int m0, int n0)
{
    __shared__ float As[2][128][20];   // [buf][m][k], pad 4 -> conflict-free
    __shared__ float Bs[2][16][132];   // [buf][k][n], pad 4

    const int tid    = threadIdx.x;
    const int lane   = tid & 31;
    const int g      = lane >> 2;     // 0..7
    const int c      = lane & 3;      // 0..3
    const int warpId = tid >> 5;
    const int wm     = warpId >> 2;   // 0..1
    const int wn     = warpId & 3;    // 0..3

    const int ar  = tid >> 2;          // 0..63 (row), second half +64
    const int akv = (tid & 3) << 2;    // k base 0,4,8,12
    const int bkr = tid >> 5;          // 0..7 (k row), second +8
    const int bnv = (tid & 31) << 2;   // n base 0..124

    const float* Ap0 = A + (size_t)(m0 + ar) * K + akv;
    const float* Ap1 = Ap0 + (size_t)64 * K;
    const float* Bp0 = W + (size_t)bkr * N + n0 + bnv;
    const float* Bp1 = Bp0 + (size_t)8 * N;

    float4 a0 = *(const float4*)Ap0;
    float4 a1 = *(const float4*)Ap1;
    float4 b0 = *(const float4*)Bp0;
    float4 b1 = *(const float4*)Bp1;

    float acc[4][4][4];
    #pragma unroll
    for (int mt = 0; mt < 4; mt++)
        #pragma unroll
        for (int nt = 0; nt < 4; nt++)
            #pragma unroll
            for (int e = 0; e < 4; e++) acc[mt][nt][e] = 0.f;

    // stage tile 0 into buffer 0
    {
        As[0][ar][akv+0]    = tf32r(a0.x); As[0][ar][akv+1]    = tf32r(a0.y);
        As[0][ar][akv+2]    = tf32r(a0.z); As[0][ar][akv+3]    = tf32r(a0.w);
        As[0][ar+64][akv+0] = tf32r(a1.x); As[0][ar+64][akv+1] = tf32r(a1.y);
        As[0][ar+64][akv+2] = tf32r(a1.z); As[0][ar+64][akv+3] = tf32r(a1.w);
        float4 tb0 = make_float4(tf32r(b0.x), tf32r(b0.y), tf32r(b0.z), tf32r(b0.w));
        float4 tb1 = make_float4(tf32r(b1.x), tf32r(b1.y), tf32r(b1.z), tf32r(b1.w));
        *(float4*)&Bs[0][bkr][bnv]   = tb0;
        *(float4*)&Bs[0][bkr+8][bnv] = tb1;
    }
    __syncthreads();

    const int NT = K >> 4;
    for (int kt = 0; kt < NT; kt++) {
        const int cur = kt & 1;
        const int nxt = cur ^ 1;

        if (kt + 1 < NT) {   // prefetch next tile into registers (overlaps mma)
            a0 = *(const float4*)(Ap0 + (kt+1)*16);
            a1 = *(const float4*)(Ap1 + (kt+1)*16);
            b0 = *(const float4*)(Bp0 + (size_t)(kt+1)*16*N);
            b1 = *(const float4*)(Bp1 + (size_t)(kt+1)*16*N);
        }

        #pragma unroll
        for (int kk = 0; kk < 16; kk += 8) {
            uint32_t af[4][4];
            #pragma unroll
            for (int mt = 0; mt < 4; mt++) {
                const int r = wm*64 + mt*16 + g;
                af[mt][0] = __float_as_uint(As[cur][r  ][kk + c]);
                af[mt][1] = __float_as_uint(As[cur][r+8][kk + c]);
                af[mt][2] = __float_as_uint(As[cur][r  ][kk + c + 4]);
                af[mt][3] = __float_as_uint(As[cur][r+8][kk + c + 4]);
            }
            uint32_t bf[4][2];
            #pragma unroll
            for (int nt = 0; nt < 4; nt++) {
                const int n = wn*32 + nt*8 + g;
                bf[nt][0] = __float_as_uint(Bs[cur][kk + c    ][n]);
                bf[nt][1] = __float_as_uint(Bs[cur][kk + c + 4][n]);
            }
            #pragma unroll
            for (int mt = 0; mt < 4; mt++)
                #pragma unroll
                for (int nt = 0; nt < 4; nt++)
                    mma_tf32(acc[mt][nt], af[mt], bf[nt]);
        }

        if (kt + 1 < NT) {   // stage next tile into the other buffer
            As[nxt][ar][akv+0]    = tf32r(a0.x); As[nxt][ar][akv+1]    = tf32r(a0.y);
            As[nxt][ar][akv+2]    = tf32r(a0.z); As[nxt][ar][akv+3]    = tf32r(a0.w);
            As[nxt][ar+64][akv+0] = tf32r(a1.x); As[nxt][ar+64][akv+1] = tf32r(a1.y);
            As[nxt][ar+64][akv+2] = tf32r(a1.z); As[nxt][ar+64][akv+3] = tf32r(a1.w);
            float4 tb0 = make_float4(tf32r(b0.x), tf32r(b0.y), tf32r(b0.z), tf32r(b0.w));
            float4 tb1 = make_float4(tf32r(b1.x), tf32r(b1.y), tf32r(b1.z), tf32r(b1.w));
            *(float4*)&Bs[nxt][bkr][bnv]   = tb0;
            *(float4*)&Bs[nxt][bkr+8][bnv] = tb1;
        }
        __syncthreads();   // nxt staged for all; cur reads done by all
    }

    #pragma unroll
    for (int nt = 0; nt < 4; nt++) {
        const int col = n0 + wn*32 + nt*8 + 2*c;
        const float bx = bias[col];
        const float by = bias[col+1];
        #pragma unroll
        for (int mt = 0; mt < 4; mt++) {
            const int r0 = m0 + wm*64 + mt*16 + g;
            float2 v0 = make_float2(acc[mt][nt][0] + bx, acc[mt][nt][1] + by);
            float2 v1 = make_float2(acc[mt][nt][2] + bx, acc[mt][nt][3] + by);
            if (PERMUTE) {
                const int h = col >> 6;          // HD = 64
                const int d = col & 63;
                {
                    const int bb = r0 >> 11;     // SEQ = 2048
                    const int t  = r0 & 2047;
                    *(float2*)&C[((size_t)(bb*NH + h) * SEQ + t) * HD + d] = v0;
                }
                {
                    const int r1 = r0 + 8;
                    const int bb = r1 >> 11;
                    const int t  = r1 & 2047;
                    *(float2*)&C[((size_t)(bb*NH + h) * SEQ + t) * HD + d] = v1;
                }
            } else {
                *(float2*)&C[(size_t)r0 * N + col]       = v0;
                *(float2*)&C[(size_t)(r0+8) * N + col]   = v1;
            }
        }
    }
}

__global__ void __launch_bounds__(256) qkv_proj_kernel(
    const float* __restrict__ A,
    const float* __restrict__ Wq, const float* __restrict__ bq, float* __restrict__ Cq,
    const float* __restrict__ Wk, const float* __restrict__ bk, float* __restrict__ Ck,
    const float* __restrict__ Wv, const float* __restrict__ bv, float* __restrict__ Cv)
{
    const float* W; const float* b; float* C;
    if (blockIdx.z == 0)      { W = Wq; b = bq; C = Cq; }
    else if (blockIdx.z == 1) { W = Wk; b = bk; C = Ck; }
    else                      { W = Wv; b = bv; C = Cv; }
    gemm_body<1>(A, W, b, C, MROWS, EMB, EMB,
                 blockIdx.y * 128, blockIdx.x * 128);
}

__global__ void __launch_bounds__(256) out_proj_kernel(
    const float* __restrict__ A, const float* __restrict__ W,
    const float* __restrict__ bias, float* __restrict__ C)
{
    gemm_body<0>(A, W, bias, C, MROWS, EMB, EMB,
                 blockIdx.y * 128, blockIdx.x * 128);
}

// Causal flash attention on the tensor pipe (tf32 mma, fp32 softmax state).
// CTA: 128 queries (8 warps x 16 rows), key tile 64. One CTA per (bh, qb).
__global__ void __launch_bounds__(256, 2) flash_kernel(
    const float* __restrict__ Q, const float* __restrict__ K,
    const float* __restrict__ V, float* __restrict__ O)
{
    extern __shared__ float sm[];
    float* Qs = sm;                 // [QT][QSS]  [row][d]
    float* Ks = Qs + QT*QSS;        // [KT][KSS]  [key][d]
    float* Vs = Ks + KT*KSS;        // [KT][VSS]  [key][d]
    float* Ps = Vs + KT*VSS;        // [QT][PSS]  [row][key]

    const int tid  = threadIdx.x;
    const int lane = tid & 31;
    const int w    = tid >> 5;       // warp 0..7 -> rows 16w..16w+15
    const int g    = lane >> 2;      // 0..7
    const int c    = lane & 3;       // 0..3
    const int bh   = blockIdx.x;
    const int qb   = (int)gridDim.y - 1 - (int)blockIdx.y;  // big tiles first
    const int q0   = qb * QT;

    const float* Qb = Q + (size_t)bh * SEQ * HD;
    const float* Kb = K + (size_t)bh * SEQ * HD;
    const float* Vb = V + (size_t)bh * SEQ * HD;

    const int lr = tid >> 4;          // 0..15
    const int ld = (tid & 15) << 2;   // 0..60

    // Load Q tile [QT][HD], fold 1/sqrt(64)=0.125, tf32-round.
    #pragma unroll
    for (int p = 0; p < 8; p++) {
        const int r = lr + p*16;
        float4 v = *(const float4*)&Qb[(size_t)(q0 + r)*HD + ld];
        Qs[r*QSS + ld+0] = tf32r(v.x * 0.125f);
        Qs[r*QSS + ld+1] = tf32r(v.y * 0.125f);
        Qs[r*QSS + ld+2] = tf32r(v.z * 0.125f);
        Qs[r*QSS + ld+3] = tf32r(v.w * 0.125f);
    }

    float m_lo = -1e30f, m_hi = -1e30f, l_lo = 0.f, l_hi = 0.f;
    float o[8][4];
    #pragma unroll
    for (int nt = 0; nt < 8; nt++)
        #pragma unroll
        for (int e = 0; e < 4; e++) o[nt][e] = 0.f;

    const int row_lo = q0 + 16*w + g;
    const int row_hi = row_lo + 8;
    const int ktn = 2*qb + 2;   // key tiles covering keys 0 .. q0+QT-1

    for (int kt = 0; kt < ktn; kt++) {
        const int k0 = kt * KT;
        // Load K,V tiles [KT][HD], tf32-round.
        #pragma unroll
        for (int p = 0; p < 4; p++) {
            const int r = lr + p*16;
            float4 kv = *(const float4*)&Kb[(size_t)(k0 + r)*HD + ld];
            Ks[r*KSS + ld+0] = tf32r(kv.x);
            Ks[r*KSS + ld+1] = tf32r(kv.y);
            Ks[r*KSS + ld+2] = tf32r(kv.z);
            Ks[r*KSS + ld+3] = tf32r(kv.w);
            float4 vv = *(const float4*)&Vb[(size_t)(k0 + r)*HD + ld];
            Vs[r*VSS + ld+0] = tf32r(vv.x);
            Vs[r*VSS + ld+1] = tf32r(vv.y);
            Vs[r*VSS + ld+2] = tf32r(vv.z);
            Vs[r*VSS + ld+3] = tf32r(vv.w);
        }
        __syncthreads();   // K/V (and first-iter Q) visible

        // ---- S = Q K^T : warp rows 16w..16w+15, all 64 keys ----
        float s[8][4];
        #pragma unroll
        for (int nt = 0; nt < 8; nt++)
            #pragma unroll
            for (int e = 0; e < 4; e++) s[nt][e] = 0.f;

        #pragma unroll
        for (int kd = 0; kd < 8; kd++) {
            uint32_t a[4];
            const int qr = (16*w + g)*QSS + kd*8;
            a[0] = __float_as_uint(Qs[qr + c]);
            a[1] = __float_as_uint(Qs[qr + 8*QSS + c]);
            a[2] = __float_as_uint(Qs[qr + c + 4]);
            a[3] = __float_as_uint(Qs[qr + 8*QSS + c + 4]);
            #pragma unroll
            for (int nt = 0; nt < 8; nt++) {
                uint32_t b[2];
                const int krr = (nt*8 + g)*KSS + kd*8;
                b[0] = __float_as_uint(Ks[krr + c]);
                b[1] = __float_as_uint(Ks[krr + c + 4]);
                mma_tf32(s[nt], a, b);
            }
        }

        // ---- causal mask (only last two tiles can overlap the diagonal) ----
        if (kt >= 2*qb) {
            #pragma unroll
            for (int nt = 0; nt < 8; nt++) {
                const int col = k0 + nt*8 + 2*c;
                if (col   > row_lo) s[nt][0] = -1e30f;
                if (col+1 > row_lo) s[nt][1] = -1e30f;
                if (col   > row_hi) s[nt][2] = -1e30f;
                if (col+1 > row_hi) s[nt][3] = -1e30f;
            }
        }

        // ---- online softmax over fragments (rows owned by 4-lane quads) ----
        float tmx_lo = -1e30f, tmx_hi = -1e30f;
        #pragma unroll
        for (int nt = 0; nt < 8; nt++) {
            tmx_lo = fmaxf(tmx_lo, fmaxf(s[nt][0], s[nt][1]));
            tmx_hi = fmaxf(tmx_hi, fmaxf(s[nt][2], s[nt][3]));
        }
        #pragma unroll
        for (int ox = 1; ox <= 2; ox <<= 1) {
            tmx_lo = fmaxf(tmx_lo, __shfl_xor_sync(0xffffffffu, tmx_lo, ox));
            tmx_hi = fmaxf(tmx_hi, __shfl_xor_sync(0xffffffffu, tmx_hi, ox));
        }
        const float mn_lo = fmaxf(m_lo, tmx_lo);
        const float mn_hi = fmaxf(m_hi, tmx_hi);
        const float cr_lo = __expf(m_lo - mn_lo);
        const float cr_hi = __expf(m_hi - mn_hi);
        m_lo = mn_lo; m_hi = mn_hi;

        float rs_lo = 0.f, rs_hi = 0.f;
        #pragma unroll
        for (int nt = 0; nt < 8; nt++) {
            float p0 = __expf(s[nt][0] - mn_lo);
            float p1 = __expf(s[nt][1] - mn_lo);
            float p2 = __expf(s[nt][2] - mn_hi);
            float p3 = __expf(s[nt][3] - mn_hi);
            rs_lo += p0 + p1;
            rs_hi += p2 + p3;
            const int pc = nt*8 + 2*c;
            *(float2*)&Ps[(16*w + g    )*PSS + pc] = make_float2(tf32r(p0), tf32r(p1));
            *(float2*)&Ps[(16*w + g + 8)*PSS + pc] = make_float2(tf32r(p2), tf32r(p3));
        }
        #pragma unroll
        for (int ox = 1; ox <= 2; ox <<= 1) {
            rs_lo += __shfl_xor_sync(0xffffffffu, rs_lo, ox);
            rs_hi += __shfl_xor_sync(0xffffffffu, rs_hi, ox);
        }
        l_lo = l_lo*cr_lo + rs_lo;
        l_hi = l_hi*cr_hi + rs_hi;
        #pragma unroll
        for (int nt = 0; nt < 8; nt++) {
            o[nt][0] *= cr_lo; o[nt][1] *= cr_lo;
            o[nt][2] *= cr_hi; o[nt][3] *= cr_hi;
        }
        __syncwarp();   // Ps rows are warp-private; warp-level fence suffices

        // ---- O += P V ----
        #pragma unroll
        for (int kd = 0; kd < 8; kd++) {
            uint32_t a[4];
            const int pr = (16*w + g)*PSS + kd*8;
            a[0] = __float_as_uint(Ps[pr + c]);
            a[1] = __float_as_uint(Ps[pr + 8*PSS + c]);
            a[2] = __float_as_uint(Ps[pr + c + 4]);
            a[3] = __float_as_uint(Ps[pr + 8*PSS + c + 4]);
            #pragma unroll
            for (int nt = 0; nt < 8; nt++) {
                uint32_t b[2];
                const int vr = (kd*8 + c)*VSS + nt*8 + g;
                b[0] = __float_as_uint(Vs[vr]);
                b[1] = __float_as_uint(Vs[vr + 4*VSS]);
                mma_tf32(o[nt], a, b);
            }
        }
        __syncthreads();   // all warps done with Ks/Vs before next tile load
    }

    // ---- epilogue: normalize and write [B,T,C] ----
    const float inv_lo = 1.f / l_lo;
    const float inv_hi = 1.f / l_hi;
    const int bb = bh >> 4;   // NH = 16
    const int h  = bh & 15;
    #pragma unroll
    for (int nt = 0; nt < 8; nt++) {
        const int col = h*HD + nt*8 + 2*c;
        *(float2*)&O[((size_t)(bb*SEQ + row_lo))*EMB + col] =
            make_float2(o[nt][0]*inv_lo, o[nt][1]*inv_lo);
        *(float2*)&O[((size_t)(bb*SEQ + row_hi))*EMB + col] =
            make_float2(o[nt][2]*inv_hi, o[nt][3]*inv_hi);
    }
}

extern "C" void kernel_launch(void* const* d_in, const int* in_sizes, int n_in,
                              void* d_out, int out_size)
{
    const float* x  = (const float*)d_in[0];
    const float* Wq = (const float*)d_in[1];
    const float* bq = (const float*)d_in[2];
    const float* Wk = (const float*)d_in[3];
    const float* bk = (const float*)d_in[4];
    const float* Wv = (const float*)d_in[5];
    const float* bv = (const float*)d_in[6];
    const float* Wo = (const float*)d_in[7];
    const float* bo = (const float*)d_in[8];
    float* out = (float*)d_out;

    float *qb, *kb, *vb, *ob;
    cudaGetSymbolAddress((void**)&qb, g_Q);
    cudaGetSymbolAddress((void**)&kb, g_K);
    cudaGetSymbolAddress((void**)&vb, g_V);
    cudaGetSymbolAddress((void**)&ob, g_O);

    dim3 gqkv(EMB/128, MROWS/128, 3);   // 768 CTAs, one launch
    qkv_proj_kernel<<<gqkv, 256>>>(x, Wq, bq, qb, Wk, bk, kb, Wv, bv, vb);

    const int smem = (QT*QSS + KT*KSS + KT*VSS + QT*PSS) * (int)sizeof(float); // 105472 B
    cudaFuncSetAttribute(flash_kernel,
                         cudaFuncAttributeMaxDynamicSharedMemorySize, smem);
    flash_kernel<<<dim3(BATCH*NH, SEQ/QT), 256, smem>>>(qb, kb, vb, ob);

    out_proj_kernel<<<dim3(EMB/128, MROWS/128), 256>>>(ob, Wo, bo, out);
}

// round 15
// speedup vs baseline: 2.8822x; 1.0467x over previous
#include <cuda_runtime.h>
#include <math.h>
#include <stdint.h>

#define BATCH 2
#define SEQ   2048
#define EMB   1024
#define NH    16
#define HD    64
#define MROWS (BATCH*SEQ)   // 4096

// flash tiling
#define QT 128
#define KT 64
#define QSS 68   // Qs stride
#define KSS 68   // Ks stride
#define VSS 72   // Vs stride
#define PSS 68   // Ps stride

// gemm B-tile stride: 136 mod 32 = 8 -> frag addr = 8c+g, bijective over lanes
#define BSS 136

// Scratch (allocation-free): Q,K,V in [B,H,T,D] packed as [(b*NH+h)*SEQ+t][HD];
// O (attention output) in [B,T,C] row-major.
__device__ float g_Q[MROWS*EMB];
__device__ float g_K[MROWS*EMB];
__device__ float g_V[MROWS*EMB];
__device__ float g_O[MROWS*EMB];

__device__ __forceinline__ float tf32r(float x) {
    uint32_t u;
    asm("cvt.rna.tf32.f32 %0, %1;" : "=r"(u) : "f"(x));
    return __uint_as_float(u);
}

__device__ __forceinline__ void mma_tf32(float d[4],
                                         const uint32_t a[4],
                                         const uint32_t b[2]) {
    asm volatile(
        "mma.sync.aligned.m16n8k8.row.col.f32.tf32.tf32.f32 "
        "{%0,%1,%2,%3}, {%4,%5,%6,%7}, {%8,%9}, {%0,%1,%2,%3};"
        : "+f"(d[0]), "+f"(d[1]), "+f"(d[2]), "+f"(d[3])
        : "r"(a[0]), "r"(a[1]), "r"(a[2]), "r"(a[3]),
          "r"(b[0]), "r"(b[1]));
}

// Tensor-core (tf32) GEMM body: C[M,N] = A @ W + bias, 128x128x16 tiles,
// 8 warps (2m x 4n), warp tile 64x32 via m16n8k8.
// Double-buffered smem, conflict-free A (stride 20) and B (stride 136) frags.
// PERMUTE=1 scatters output into [B,H,T,D].
template<int PERMUTE>
__device__ __forceinline__ void gemm_body(
    const float* __restrict__ A, const float* __restrict__ W,
    const float* __restrict__ bias, float* __restrict__ C,
    int M, int N, int K, int m0, int n0)
{
    __shared__ float As[2][128][20];    // [buf][m][k]
    __shared__ float Bs[2][16][BSS];    // [buf][k][n]

    const int tid    = threadIdx.x;
    const int lane   = tid & 31;
    const int g      = lane >> 2;     // 0..7
    const int c      = lane & 3;      // 0..3
    const int warpId = tid >> 5;
    const int wm     = warpId >> 2;   // 0..1
    const int wn     = warpId & 3;    // 0..3

    const int ar  = tid >> 2;          // 0..63 (row), second half +64
    const int akv = (tid & 3) << 2;    // k base 0,4,8,12
    const int bkr = tid >> 5;          // 0..7 (k row), second +8
    const int bnv = (tid & 31) << 2;   // n base 0..124

    const float* Ap0 = A + (size_t)(m0 + ar) * K + akv;
    const float* Ap1 = Ap0 + (size_t)64 * K;
    const float* Bp0 = W + (size_t)bkr * N + n0 + bnv;
    const float* Bp1 = Bp0 + (size_t)8 * N;

    float4 a0 = *(const float4*)Ap0;
    float4 a1 = *(const float4*)Ap1;
    float4 b0 = *(const float4*)Bp0;
    float4 b1 = *(const float4*)Bp1;

    float acc[4][4][4];
    #pragma unroll
    for (int mt = 0; mt < 4; mt++)
        #pragma unroll
        for (int nt = 0; nt < 4; nt++)
            #pragma unroll
            for (int e = 0; e < 4; e++) acc[mt][nt][e] = 0.f;

    // stage tile 0 into buffer 0
    {
        *(float4*)&As[0][ar][akv] =
            make_float4(tf32r(a0.x), tf32r(a0.y), tf32r(a0.z), tf32r(a0.w));
        *(float4*)&As[0][ar+64][akv] =
            make_float4(tf32r(a1.x), tf32r(a1.y), tf32r(a1.z), tf32r(a1.w));
        *(float4*)&Bs[0][bkr][bnv] =
            make_float4(tf32r(b0.x), tf32r(b0.y), tf32r(b0.z), tf32r(b0.w));
        *(float4*)&Bs[0][bkr+8][bnv] =
            make_float4(tf32r(b1.x), tf32r(b1.y), tf32r(b1.z), tf32r(b1.w));
    }
    __syncthreads();

    const int NT = K >> 4;
    for (int kt = 0; kt < NT; kt++) {
        const int cur = kt & 1;
        const int nxt = cur ^ 1;

        if (kt + 1 < NT) {   // prefetch next tile into registers (overlaps mma)
            a0 = *(const float4*)(Ap0 + (kt+1)*16);
            a1 = *(const float4*)(Ap1 + (kt+1)*16);
            b0 = *(const float4*)(Bp0 + (size_t)(kt+1)*16*N);
            b1 = *(const float4*)(Bp1 + (size_t)(kt+1)*16*N);
        }

        #pragma unroll
        for (int kk = 0; kk < 16; kk += 8) {
            uint32_t af[4][4];
            #pragma unroll
            for (int mt = 0; mt < 4; mt++) {
                const int r = wm*64 + mt*16 + g;
                af[mt][0] = __float_as_uint(As[cur][r  ][kk + c]);
                af[mt][1] = __float_as_uint(As[cur][r+8][kk + c]);
                af[mt][2] = __float_as_uint(As[cur][r  ][kk + c + 4]);
                af[mt][3] = __float_as_uint(As[cur][r+8][kk + c + 4]);
            }
            uint32_t bf[4][2];
            #pragma unroll
            for (int nt = 0; nt < 4; nt++) {
                const int n = wn*32 + nt*8 + g;
                bf[nt][0] = __float_as_uint(Bs[cur][kk + c    ][n]);
                bf[nt][1] = __float_as_uint(Bs[cur][kk + c + 4][n]);
            }
            #pragma unroll
            for (int mt = 0; mt < 4; mt++)
                #pragma unroll
                for (int nt = 0; nt < 4; nt++)
                    mma_tf32(acc[mt][nt], af[mt], bf[nt]);
        }

        if (kt + 1 < NT) {   // stage next tile into the other buffer
            *(float4*)&As[nxt][ar][akv] =
                make_float4(tf32r(a0.x), tf32r(a0.y), tf32r(a0.z), tf32r(a0.w));
            *(float4*)&As[nxt][ar+64][akv] =
                make_float4(tf32r(a1.x), tf32r(a1.y), tf32r(a1.z), tf32r(a1.w));
            *(float4*)&Bs[nxt][bkr][bnv] =
                make_float4(tf32r(b0.x), tf32r(b0.y), tf32r(b0.z), tf32r(b0.w));
            *(float4*)&Bs[nxt][bkr+8][bnv] =
                make_float4(tf32r(b1.x), tf32r(b1.y), tf32r(b1.z), tf32r(b1.w));
        }
        __syncthreads();   // nxt staged for all; cur reads done by all
    }

    #pragma unroll
    for (int nt = 0; nt < 4; nt++) {
        const int col = n0 + wn*32 + nt*8 + 2*c;
        const float bx = bias[col];
        const float by = bias[col+1];
        #pragma unroll
        for (int mt = 0; mt < 4; mt++) {
            const int r0 = m0 + wm*64 + mt*16 + g;
            float2 v0 = make_float2(acc[mt][nt][0] + bx, acc[mt][nt][1] + by);
            float2 v1 = make_float2(acc[mt][nt][2] + bx, acc[mt][nt][3] + by);
            if (PERMUTE) {
                const int h = col >> 6;          // HD = 64
                const int d = col & 63;
                {
                    const int bb = r0 >> 11;     // SEQ = 2048
                    const int t  = r0 & 2047;
                    *(float2*)&C[((size_t)(bb*NH + h) * SEQ + t) * HD + d] = v0;
                }
                {
                    const int r1 = r0 + 8;
                    const int bb = r1 >> 11;
                    const int t  = r1 & 2047;
                    *(float2*)&C[((size_t)(bb*NH + h) * SEQ + t) * HD + d] = v1;
                }
            } else {
                *(float2*)&C[(size_t)r0 * N + col]       = v0;
                *(float2*)&C[(size_t)(r0+8) * N + col]   = v1;
            }
        }
    }
}

__global__ void __launch_bounds__(256) qkv_proj_kernel(
    const float* __restrict__ A,
    const float* __restrict__ Wq, const float* __restrict__ bq, float* __restrict__ Cq,
    const float* __restrict__ Wk, const float* __restrict__ bk, float* __restrict__ Ck,
    const float* __restrict__ Wv, const float* __restrict__ bv, float* __restrict__ Cv)
{
    const float* W; const float* b; float* C;
    if (blockIdx.z == 0)      { W = Wq; b = bq; C = Cq; }
    else if (blockIdx.z == 1) { W = Wk; b = bk; C = Ck; }
    else                      { W = Wv; b = bv; C = Cv; }
    gemm_body<1>(A, W, b, C, MROWS, EMB, EMB,
                 blockIdx.y * 128, blockIdx.x * 128);
}

__global__ void __launch_bounds__(256) out_proj_kernel(
    const float* __restrict__ A, const float* __restrict__ W,
    const float* __restrict__ bias, float* __restrict__ C)
{
    gemm_body<0>(A, W, bias, C, MROWS, EMB, EMB,
                 blockIdx.y * 128, blockIdx.x * 128);
}

// Causal flash attention on the tensor pipe (tf32 mma, fp32 softmax state).
// CTA: 128 queries (8 warps x 16 rows), key tile 64. One CTA per (bh, qb).
__global__ void __launch_bounds__(256, 2) flash_kernel(
    const float* __restrict__ Q, const float* __restrict__ K,
    const float* __restrict__ V, float* __restrict__ O)
{
    extern __shared__ float sm[];
    float* Qs = sm;                 // [QT][QSS]  [row][d]
    float* Ks = Qs + QT*QSS;        // [KT][KSS]  [key][d]
    float* Vs = Ks + KT*KSS;        // [KT][VSS]  [key][d]
    float* Ps = Vs + KT*VSS;        // [QT][PSS]  [row][key]

    const int tid  = threadIdx.x;
    const int lane = tid & 31;
    const int w    = tid >> 5;       // warp 0..7 -> rows 16w..16w+15
    const int g    = lane >> 2;      // 0..7
    const int c    = lane & 3;       // 0..3
    const int bh   = blockIdx.x;
    const int qb   = (int)gridDim.y - 1 - (int)blockIdx.y;  // big tiles first
    const int q0   = qb * QT;

    const float* Qb = Q + (size_t)bh * SEQ * HD;
    const float* Kb = K + (size_t)bh * SEQ * HD;
    const float* Vb = V + (size_t)bh * SEQ * HD;

    const int lr = tid >> 4;          // 0..15
    const int ld = (tid & 15) << 2;   // 0..60

    // Load Q tile [QT][HD], fold 1/sqrt(64)=0.125, tf32-round.
    #pragma unroll
    for (int p = 0; p < 8; p++) {
        const int r = lr + p*16;
        float4 v = *(const float4*)&Qb[(size_t)(q0 + r)*HD + ld];
        Qs[r*QSS + ld+0] = tf32r(v.x * 0.125f);
        Qs[r*QSS + ld+1] = tf32r(v.y * 0.125f);
        Qs[r*QSS + ld+2] = tf32r(v.z * 0.125f);
        Qs[r*QSS + ld+3] = tf32r(v.w * 0.125f);
    }

    float m_lo = -1e30f, m_hi = -1e30f, l_lo = 0.f, l_hi = 0.f;
    float o[8][4];
    #pragma unroll
    for (int nt = 0; nt < 8; nt++)
        #pragma unroll
        for (int e = 0; e < 4; e++) o[nt][e] = 0.f;

    const int row_lo = q0 + 16*w + g;
    const int row_hi = row_lo + 8;
    const int ktn = 2*qb + 2;   // key tiles covering keys 0 .. q0+QT-1

    for (int kt = 0; kt < ktn; kt++) {
        const int k0 = kt * KT;
        // Load K,V tiles [KT][HD], tf32-round.
        #pragma unroll
        for (int p = 0; p < 4; p++) {
            const int r = lr + p*16;
            float4 kv = *(const float4*)&Kb[(size_t)(k0 + r)*HD + ld];
            Ks[r*KSS + ld+0] = tf32r(kv.x);
            Ks[r*KSS + ld+1] = tf32r(kv.y);
            Ks[r*KSS + ld+2] = tf32r(kv.z);
            Ks[r*KSS + ld+3] = tf32r(kv.w);
            float4 vv = *(const float4*)&Vb[(size_t)(k0 + r)*HD + ld];
            Vs[r*VSS + ld+0] = tf32r(vv.x);
            Vs[r*VSS + ld+1] = tf32r(vv.y);
            Vs[r*VSS + ld+2] = tf32r(vv.z);
            Vs[r*VSS + ld+3] = tf32r(vv.w);
        }
        __syncthreads();   // K/V (and first-iter Q) visible

        // ---- S = Q K^T : warp rows 16w..16w+15, all 64 keys ----
        float s[8][4];
        #pragma unroll
        for (int nt = 0; nt < 8; nt++)
            #pragma unroll
            for (int e = 0; e < 4; e++) s[nt][e] = 0.f;

        #pragma unroll
        for (int kd = 0; kd < 8; kd++) {
            uint32_t a[4];
            const int qr = (16*w + g)*QSS + kd*8;
            a[0] = __float_as_uint(Qs[qr + c]);
            a[1] = __float_as_uint(Qs[qr + 8*QSS + c]);
            a[2] = __float_as_uint(Qs[qr + c + 4]);
            a[3] = __float_as_uint(Qs[qr + 8*QSS + c + 4]);
            #pragma unroll
            for (int nt = 0; nt < 8; nt++) {
                uint32_t b[2];
                const int krr = (nt*8 + g)*KSS + kd*8;
                b[0] = __float_as_uint(Ks[krr + c]);
                b[1] = __float_as_uint(Ks[krr + c + 4]);
                mma_tf32(s[nt], a, b);
            }
        }

        // ---- causal mask (only last two tiles can overlap the diagonal) ----
        if (kt >= 2*qb) {
            #pragma unroll
            for (int nt = 0; nt < 8; nt++) {
                const int col = k0 + nt*8 + 2*c;
                if (col   > row_lo) s[nt][0] = -1e30f;
                if (col+1 > row_lo) s[nt][1] = -1e30f;
                if (col   > row_hi) s[nt][2] = -1e30f;
                if (col+1 > row_hi) s[nt][3] = -1e30f;
            }
        }

        // ---- online softmax over fragments (rows owned by 4-lane quads) ----
        float tmx_lo = -1e30f, tmx_hi = -1e30f;
        #pragma unroll
        for (int nt = 0; nt < 8; nt++) {
            tmx_lo = fmaxf(tmx_lo, fmaxf(s[nt][0], s[nt][1]));
            tmx_hi = fmaxf(tmx_hi, fmaxf(s[nt][2], s[nt][3]));
        }
        #pragma unroll
        for (int ox = 1; ox <= 2; ox <<= 1) {
            tmx_lo = fmaxf(tmx_lo, __shfl_xor_sync(0xffffffffu, tmx_lo, ox));
            tmx_hi = fmaxf(tmx_hi, __shfl_xor_sync(0xffffffffu, tmx_hi, ox));
        }
        const float mn_lo = fmaxf(m_lo, tmx_lo);
        const float mn_hi = fmaxf(m_hi, tmx_hi);
        const float cr_lo = __expf(m_lo - mn_lo);
        const float cr_hi = __expf(m_hi - mn_hi);
        m_lo = mn_lo; m_hi = mn_hi;

        float rs_lo = 0.f, rs_hi = 0.f;
        #pragma unroll
        for (int nt = 0; nt < 8; nt++) {
            float p0 = __expf(s[nt][0] - mn_lo);
            float p1 = __expf(s[nt][1] - mn_lo);
            float p2 = __expf(s[nt][2] - mn_hi);
            float p3 = __expf(s[nt][3] - mn_hi);
            rs_lo += p0 + p1;
            rs_hi += p2 + p3;
            const int pc = nt*8 + 2*c;
            *(float2*)&Ps[(16*w + g    )*PSS + pc] = make_float2(tf32r(p0), tf32r(p1));
            *(float2*)&Ps[(16*w + g + 8)*PSS + pc] = make_float2(tf32r(p2), tf32r(p3));
        }
        #pragma unroll
        for (int ox = 1; ox <= 2; ox <<= 1) {
            rs_lo += __shfl_xor_sync(0xffffffffu, rs_lo, ox);
            rs_hi += __shfl_xor_sync(0xffffffffu, rs_hi, ox);
        }
        l_lo = l_lo*cr_lo + rs_lo;
        l_hi = l_hi*cr_hi + rs_hi;
        #pragma unroll
        for (int nt = 0; nt < 8; nt++) {
            o[nt][0] *= cr_lo; o[nt][1] *= cr_lo;
            o[nt][2] *= cr_hi; o[nt][3] *= cr_hi;
        }
        __syncwarp();   // Ps rows are warp-private; warp-level fence suffices

        // ---- O += P V ----
        #pragma unroll
        for (int kd = 0; kd < 8; kd++) {
            uint32_t a[4];
            const int pr = (16*w + g)*PSS + kd*8;
            a[0] = __float_as_uint(Ps[pr + c]);
            a[1] = __float_as_uint(Ps[pr + 8*PSS + c]);
            a[2] = __float_as_uint(Ps[pr + c + 4]);
            a[3] = __float_as_uint(Ps[pr + 8*PSS + c + 4]);
            #pragma unroll
            for (int nt = 0; nt < 8; nt++) {
                uint32_t b[2];
                const int vr = (kd*8 + c)*VSS + nt*8 + g;
                b[0] = __float_as_uint(Vs[vr]);
                b[1] = __float_as_uint(Vs[vr + 4*VSS]);
                mma_tf32(o[nt], a, b);
            }
        }
        __syncthreads();   // all warps done with Ks/Vs before next tile load
    }

    // ---- epilogue: normalize and write [B,T,C] ----
    const float inv_lo = 1.f / l_lo;
    const float inv_hi = 1.f / l_hi;
    const int bb = bh >> 4;   // NH = 16
    const int h  = bh & 15;
    #pragma unroll
    for (int nt = 0; nt < 8; nt++) {
        const int col = h*HD + nt*8 + 2*c;
        *(float2*)&O[((size_t)(bb*SEQ + row_lo))*EMB + col] =
            make_float2(o[nt][0]*inv_lo, o[nt][1]*inv_lo);
        *(float2*)&O[((size_t)(bb*SEQ + row_hi))*EMB + col] =
            make_float2(o[nt][2]*inv_hi, o[nt][3]*inv_hi);
    }
}

extern "C" void kernel_launch(void* const* d_in, const int* in_sizes, int n_in,
                              void* d_out, int out_size)
{
    const float* x  = (const float*)d_in[0];
    const float* Wq = (const float*)d_in[1];
    const float* bq = (const float*)d_in[2];
    const float* Wk = (const float*)d_in[3];
    const float* bk = (const float*)d_in[4];
    const float* Wv = (const float*)d_in[5];
    const float* bv = (const float*)d_in[6];
    const float* Wo = (const float*)d_in[7];
    const float* bo = (const float*)d_in[8];
    float* out = (float*)d_out;

    float *qb, *kb, *vb, *ob;
    cudaGetSymbolAddress((void**)&qb, g_Q);
    cudaGetSymbolAddress((void**)&kb, g_K);
    cudaGetSymbolAddress((void**)&vb, g_V);
    cudaGetSymbolAddress((void**)&ob, g_O);

    dim3 gqkv(EMB/128, MROWS/128, 3);   // 768 CTAs, one launch
    qkv_proj_kernel<<<gqkv, 256>>>(x, Wq, bq, qb, Wk, bk, kb, Wv, bv, vb);

    const int smem = (QT*QSS + KT*KSS + KT*VSS + QT*PSS) * (int)sizeof(float); // 105472 B
    cudaFuncSetAttribute(flash_kernel,
                         cudaFuncAttributeMaxDynamicSharedMemorySize, smem);
    flash_kernel<<<dim3(BATCH*NH, SEQ/QT), 256, smem>>>(qb, kb, vb, ob);

    out_proj_kernel<<<dim3(EMB/128, MROWS/128), 256>>>(ob, Wo, bo, out);
}